// round 12
// baseline (speedup 1.0000x reference)
#include <cuda_runtime.h>
#include <cuda_bf16.h>
#include <math.h>
#include <stdint.h>

// ---------------- problem constants ----------------
#define BSZ   8
#define IMG   128
#define DIM   128
#define HEADS 4
#define HD    32
#define NLAYERS 2
#define PC    8
#define PF    4
#define HC    16
#define NC    256
#define HF    32
#define NF    1024
#define NTOK  1280           // NC + NF
#define MROWS (BSZ*NTOK)     // 10240

// ---------------- scratch (allocation-free) ----------------
__device__ float g_tokens[MROWS*DIM];
__device__ float g_y     [MROWS*DIM];
__device__ float g_qkv   [MROWS*3*DIM];
__device__ float g_attn  [MROWS*DIM];        // flash partial, key half 0 (unnormalized)
__device__ float g_attn2 [MROWS*DIM];        // flash partial, key half 1 (unnormalized)
__device__ float g_l     [2*MROWS*HEADS];    // softmax denominators [half][row][head]
__device__ float g_h     [MROWS*2*DIM];
__device__ int   g_order [BSZ*NF];
__device__ int   g_nedges[BSZ];
__device__ float g_c16map[BSZ*NC];           // decoder coarse head output
__device__ float g_fmap  [BSZ*NF];           // decoder fine head output (pixel order)

#define BUF_TOKENS 0
#define BUF_Y      1
#define BUF_QKV    2
#define BUF_ATTN   3
#define BUF_H      4

__device__ __forceinline__ float* bufsel(int s) {
    switch (s) {
        case BUF_TOKENS: return g_tokens;
        case BUF_Y:      return g_y;
        case BUF_QKV:    return g_qkv;
        case BUF_ATTN:   return g_attn;
        case BUF_H:      return g_h;
    }
    return nullptr;
}

// ---------------- mma helpers ----------------
__device__ __forceinline__ uint32_t f2tf(float x) {
    uint32_t u;
    asm("cvt.rna.tf32.f32 %0, %1;" : "=r"(u) : "f"(x));
    return u;
}

__device__ __forceinline__ void mma_tf32(float* c, const uint32_t* a, const uint32_t* b) {
    asm volatile(
        "mma.sync.aligned.m16n8k8.row.col.f32.tf32.tf32.f32 "
        "{%0,%1,%2,%3}, {%4,%5,%6,%7}, {%8,%9}, {%0,%1,%2,%3};\n"
        : "+f"(c[0]), "+f"(c[1]), "+f"(c[2]), "+f"(c[3])
        : "r"(a[0]), "r"(a[1]), "r"(a[2]), "r"(a[3]), "r"(b[0]), "r"(b[1]));
}

__device__ __forceinline__ void mma_bf16(float* c, const uint32_t* a, const uint32_t* b) {
    asm volatile(
        "mma.sync.aligned.m16n8k16.row.col.f32.bf16.bf16.f32 "
        "{%0,%1,%2,%3}, {%4,%5,%6,%7}, {%8,%9}, {%0,%1,%2,%3};\n"
        : "+f"(c[0]), "+f"(c[1]), "+f"(c[2]), "+f"(c[3])
        : "r"(a[0]), "r"(a[1]), "r"(a[2]), "r"(a[3]), "r"(b[0]), "r"(b[1]));
}

// pack two floats into bf16x2: low half = lo, high half = hi
__device__ __forceinline__ uint32_t pack_bf16(float lo, float hi) {
    uint32_t d;
    asm("cvt.rn.bf16x2.f32 %0, %1, %2;" : "=r"(d) : "f"(hi), "f"(lo));
    return d;
}

__device__ __forceinline__ void ldm_x4(uint32_t& r0, uint32_t& r1, uint32_t& r2, uint32_t& r3,
                                       uint32_t addr) {
    asm volatile("ldmatrix.sync.aligned.m8n8.x4.shared.b16 {%0,%1,%2,%3}, [%4];"
        : "=r"(r0), "=r"(r1), "=r"(r2), "=r"(r3) : "r"(addr));
}

// ---------------- edge map + stable partition order (ballot scan) ----------------
__device__ __forceinline__ float padpx(const float* m, int y, int x) {
    return (y < 0 || y >= IMG || x < 0 || x >= IMG) ? 0.f : m[y*IMG + x];
}

__global__ void edge_kernel(const float* __restrict__ x) {
    int b = blockIdx.x, t = threadIdx.x;           // t in [0,1024)
    const float* img = x + b*IMG*IMG;
    int gy = t >> 5, gx = t & 31;
    float e = 0.f;
    #pragma unroll
    for (int wy = 0; wy < 4; wy++) {
        #pragma unroll
        for (int wx = 0; wx < 4; wx++) {
            int y = gy*4 + wy, xx = gx*4 + wx;
            float sx = padpx(img,y-1,xx+1) - padpx(img,y-1,xx-1)
                     + 2.f*(padpx(img,y,xx+1) - padpx(img,y,xx-1))
                     + padpx(img,y+1,xx+1) - padpx(img,y+1,xx-1);
            float sy = padpx(img,y+1,xx-1) + 2.f*padpx(img,y+1,xx) + padpx(img,y+1,xx+1)
                     - padpx(img,y-1,xx-1) - 2.f*padpx(img,y-1,xx) - padpx(img,y-1,xx+1);
            e += sqrtf(sx*sx + sy*sy);
        }
    }
    e *= (1.f/16.f);

    int w = t >> 5, lane = t & 31;
    __shared__ float wsumf[32];
    __shared__ int   wsum [32];
    __shared__ float smean;
    __shared__ int   s_ne;

    float s = e;
    #pragma unroll
    for (int off = 16; off > 0; off >>= 1) s += __shfl_xor_sync(0xffffffffu, s, off);
    if (lane == 0) wsumf[w] = s;
    __syncthreads();
    if (w == 0) {
        float v = wsumf[lane];
        #pragma unroll
        for (int off = 16; off > 0; off >>= 1) v += __shfl_xor_sync(0xffffffffu, v, off);
        if (lane == 0) smean = v * (1.f/1024.f);
    }
    __syncthreads();

    int mk = (e > smean) ? 1 : 0;
    unsigned bal = __ballot_sync(0xffffffffu, mk);
    unsigned lemask = 0xffffffffu >> (31 - lane);
    int rank_in_warp = __popc(bal & lemask);
    if (lane == 0) wsum[w] = __popc(bal);
    __syncthreads();
    if (w == 0) {
        int v = wsum[lane];
        #pragma unroll
        for (int off = 1; off < 32; off <<= 1) {
            int n = __shfl_up_sync(0xffffffffu, v, off);
            if (lane >= off) v += n;
        }
        wsum[lane] = v;
        if (lane == 31) s_ne = v;
    }
    __syncthreads();
    int prefix = (w > 0) ? wsum[w-1] : 0;
    int rank = prefix + rank_in_warp;
    int ne = s_ne;
    int pos = mk ? (rank - 1) : (ne + t - rank);
    g_order[b*NF + pos] = t;
    if (t == 0) g_nedges[b] = ne;
}

// ---------------- patch embed + token assembly + fused first LN ----------------
__global__ void patch_kernel(const float* __restrict__ x,
                             const float* __restrict__ Wpc, const float* __restrict__ bpc,
                             const float* __restrict__ Wpf, const float* __restrict__ bpf,
                             const float* __restrict__ te,
                             const float* __restrict__ lng, const float* __restrict__ lnb) {
    int blk = blockIdx.x;
    int b = blk / NTOK, t = blk % NTOK;
    int d = threadIdx.x;                 // 128
    const float* img = x + b*IMG*IMG;
    __shared__ float sp[64];
    float acc;

    if (t < NC) {
        int hp = t / HC, wp = t % HC;
        if (d < 64) {
            int py = d >> 3, px = d & 7;
            sp[d] = img[(hp*PC + py)*IMG + wp*PC + px];
        }
        __syncthreads();
        acc = bpc[d] + te[d];
        #pragma unroll 8
        for (int p = 0; p < 64; p++) acc += sp[p] * Wpc[p*DIM + d];
    } else {
        int p  = t - NC;
        int ne = g_nedges[b];
        acc = te[DIM + d];
        if (p < ne) {
            int ord = g_order[b*NF + p];
            int hp = ord / HF, wp = ord % HF;
            if (d < 16) {
                int py = d >> 2, px = d & 3;
                sp[d] = img[(hp*PF + py)*IMG + wp*PF + px];
            }
            __syncthreads();
            acc += bpf[d];
            #pragma unroll
            for (int e = 0; e < 16; e++) acc += sp[e] * Wpf[e*DIM + d];
        }
    }

    float v = acc;
    float s = v, q = v*v;
    #pragma unroll
    for (int off = 16; off > 0; off >>= 1) {
        s += __shfl_down_sync(0xffffffffu, s, off);
        q += __shfl_down_sync(0xffffffffu, q, off);
    }
    __shared__ float ss[4], qq[4];
    int w = d >> 5, lane = d & 31;
    if (lane == 0) { ss[w] = s; qq[w] = q; }
    __syncthreads();
    float S = ss[0]+ss[1]+ss[2]+ss[3];
    float Q = qq[0]+qq[1]+qq[2]+qq[3];
    float mean = S * (1.f/DIM);
    float var  = Q * (1.f/DIM) - mean*mean;
    int row = b*NTOK + t;
    g_tokens[row*DIM + d] = v;
    g_y[row*DIM + d] = (v - mean) * rsqrtf(var + 1e-5f) * lng[d] + lnb[d];
}

// ---------------- tf32 tensor-core GEMM ----------------
template<int BM, int BN, int THREADS, int ACT, bool RES, bool LNOUT, bool COMBINE>
__global__ void __launch_bounds__(THREADS) gemm_tc(
        int aSel, const float* __restrict__ Bw, const float* __restrict__ bias,
        int resSel, int outSel, int N, int K,
        const float* __restrict__ lng, const float* __restrict__ lnb) {
    const float* A = bufsel(aSel);
    float* C = bufsel(outSel);
    const float* R = RES ? bufsel(resSel) : nullptr;

    constexpr int WARPS = THREADS/32;
    constexpr int WN = BN/32;
    constexpr int WM = WARPS/WN;
    static_assert(BM/WM == 32, "rows-per-warp must be 32");

    constexpr int APAD = BM + 8;
    constexpr int BPAD = BN + 8;
    constexpr int CPAD = BN + 5;
    constexpr int ABYTES = 16*APAD*4;
    constexpr int BBYTES = 16*BPAD*4;
    constexpr int CBYTES = LNOUT ? BM*CPAD*4 : 0;
    constexpr int SBYTES = (ABYTES+BBYTES) > CBYTES ? (ABYTES+BBYTES) : CBYTES;
    __shared__ alignas(16) char raw[SBYTES];
    uint32_t (*As)[APAD] = reinterpret_cast<uint32_t(*)[APAD]>(raw);
    uint32_t (*Bs)[BPAD] = reinterpret_cast<uint32_t(*)[BPAD]>(raw + ABYTES);
    float    (*Cs)[CPAD] = reinterpret_cast<float(*)[CPAD]>(raw);
    __shared__ float s_mu[BM], s_rs[BM];
    __shared__ float s_rinv[COMBINE ? BM*HEADS : 1];

    int tid = threadIdx.x;
    int lane = tid & 31;
    int w = tid >> 5;
    int wm = w / WN;
    int wn = w % WN;
    int g  = lane >> 2;
    int t4 = lane & 3;

    int row0 = blockIdx.y * BM;
    int col0 = blockIdx.x * BN;

    if (COMBINE) {
        if (tid < BM*HEADS) {
            int r  = row0 + tid/HEADS;
            int hh = tid % HEADS;
            s_rinv[tid] = 1.f / (g_l[r*HEADS + hh] + g_l[(MROWS + r)*HEADS + hh]);
        }
        __syncthreads();
    }

    float acc[2][4][4];
    #pragma unroll
    for (int mt = 0; mt < 2; mt++)
        #pragma unroll
        for (int nt = 0; nt < 4; nt++)
            #pragma unroll
            for (int i = 0; i < 4; i++) acc[mt][nt][i] = 0.f;

    for (int k0 = 0; k0 < K; k0 += 16) {
        #pragma unroll
        for (int i = 0; i < BM*16/(THREADS*4); i++) {
            int lin = tid + i*THREADS;
            int row = lin >> 2;
            int kq  = lin & 3;
            int idx = (row0 + row)*K + k0 + kq*4;
            float4 v;
            if (COMBINE) {
                float4 va = *reinterpret_cast<const float4*>(&g_attn [idx]);
                float4 vb = *reinterpret_cast<const float4*>(&g_attn2[idx]);
                float ri = s_rinv[row*HEADS + ((k0 + kq*4) >> 5)];
                v.x = (va.x+vb.x)*ri; v.y = (va.y+vb.y)*ri;
                v.z = (va.z+vb.z)*ri; v.w = (va.w+vb.w)*ri;
            } else {
                v = *reinterpret_cast<const float4*>(&A[idx]);
            }
            As[kq*4+0][row] = f2tf(v.x);
            As[kq*4+1][row] = f2tf(v.y);
            As[kq*4+2][row] = f2tf(v.z);
            As[kq*4+3][row] = f2tf(v.w);
        }
        #pragma unroll
        for (int i = 0; i < BN*16/(THREADS*4); i++) {
            int lin = tid + i*THREADS;
            int k  = lin / (BN/4);
            int cq = lin % (BN/4);
            float4 v = *reinterpret_cast<const float4*>(&Bw[(k0 + k)*N + col0 + cq*4]);
            uint4 u;
            u.x = f2tf(v.x); u.y = f2tf(v.y); u.z = f2tf(v.z); u.w = f2tf(v.w);
            *reinterpret_cast<uint4*>(&Bs[k][cq*4]) = u;
        }
        __syncthreads();

        #pragma unroll
        for (int ks = 0; ks < 2; ks++) {
            int kk = ks*8;
            uint32_t af[2][4], bf[4][2];
            #pragma unroll
            for (int mt = 0; mt < 2; mt++) {
                int br = wm*32 + mt*16;
                af[mt][0] = As[kk + t4    ][br + g    ];
                af[mt][1] = As[kk + t4    ][br + g + 8];
                af[mt][2] = As[kk + t4 + 4][br + g    ];
                af[mt][3] = As[kk + t4 + 4][br + g + 8];
            }
            #pragma unroll
            for (int nt = 0; nt < 4; nt++) {
                int bc = wn*32 + nt*8;
                bf[nt][0] = Bs[kk + t4    ][bc + g];
                bf[nt][1] = Bs[kk + t4 + 4][bc + g];
            }
            #pragma unroll
            for (int mt = 0; mt < 2; mt++)
                #pragma unroll
                for (int nt = 0; nt < 4; nt++)
                    mma_tf32(acc[mt][nt], af[mt], bf[nt]);
        }
        __syncthreads();
    }

    #pragma unroll
    for (int mt = 0; mt < 2; mt++) {
        #pragma unroll
        for (int nt = 0; nt < 4; nt++) {
            #pragma unroll
            for (int half = 0; half < 2; half++) {
                int lr = wm*32 + mt*16 + g + half*8;
                int lc = wn*32 + nt*8 + t4*2;
                int r  = row0 + lr;
                int c  = col0 + lc;
                float v0 = acc[mt][nt][half*2+0];
                float v1 = acc[mt][nt][half*2+1];
                if (bias) { v0 += bias[c]; v1 += bias[c+1]; }
                if (ACT == 1) {
                    v0 = 0.5f*v0*(1.f + erff(v0*0.70710678118654752f));
                    v1 = 0.5f*v1*(1.f + erff(v1*0.70710678118654752f));
                }
                if (RES) { v0 += R[r*N + c]; v1 += R[r*N + c + 1]; }
                float2 st; st.x = v0; st.y = v1;
                *reinterpret_cast<float2*>(&C[r*N + c]) = st;
                if (LNOUT) { Cs[lr][lc] = v0; Cs[lr][lc+1] = v1; }
            }
        }
    }

    if (LNOUT) {
        __syncthreads();
        if (tid < BM) {
            float s = 0.f, q = 0.f;
            #pragma unroll 8
            for (int c = 0; c < BN; c++) {
                float v = Cs[tid][c];
                s += v; q += v*v;
            }
            float mean = s * (1.f/BN);
            float var  = q * (1.f/BN) - mean*mean;
            s_mu[tid] = mean;
            s_rs[tid] = rsqrtf(var + 1e-5f);
        }
        __syncthreads();
        #pragma unroll
        for (int i = 0; i < BM*BN/THREADS; i++) {
            int lin = tid + i*THREADS;
            int r = lin / BN;
            int c = lin % BN;
            float v = (Cs[r][c] - s_mu[r]) * s_rs[r] * lng[c] + lnb[c];
            g_y[(row0 + r)*BN + c] = v;
        }
    }
}

// ---------------- bf16 tensor-core flash attention (key-split x2, ldmatrix) ----------------
// One block per (b, h, 64-query tile, key-half). 4 warps x 16 q-rows.
// B-fragments loaded via ldmatrix.m8n8.x4 (conflict-free: K rows 80B stride,
// Vt rows 144B stride -> disjoint bank phases).
#define QR 64     // q rows per block
#define KT 64     // keys per staged tile
#define QSP 40    // Q row stride (bf16) = 80B (16B-aligned)
#define KSP 40    // K row stride (bf16) = 80B
#define VSP 72    // Vt row stride (bf16) = 144B
__global__ void __launch_bounds__(128) flash_bf16_kernel() {
    __shared__ alignas(16) uint16_t Qs[QR][QSP];
    __shared__ alignas(16) uint16_t Ks[KT][KSP];
    __shared__ alignas(16) uint16_t Vt[HD][VSP];

    int tid = threadIdx.x;
    int lane = tid & 31;
    int w = tid >> 5;                 // 0..3
    int g = lane >> 2;                // 0..7
    int t4 = lane & 3;                // 0..3
    int lrow = lane & 7;              // ldmatrix row provider
    int lquad = (lane >> 3) * 16;     // ldmatrix 16B column offset

    int half = blockIdx.x & 1;
    int rest = blockIdx.x >> 1;
    int qt = rest % (NTOK/QR);                  // 0..19
    int h  = (rest / (NTOK/QR)) % HEADS;
    int b  = rest / ((NTOK/QR)*HEADS);
    int row0 = b*NTOK + qt*QR;
    const float scale = 0.17677669529663687f;   // 1/sqrt(32)

    uint32_t ks_base = (uint32_t)__cvta_generic_to_shared(&Ks[0][0]);
    uint32_t vt_base = (uint32_t)__cvta_generic_to_shared(&Vt[0][0]);

    // ---- stage Q (64 x 32), scaled, bf16 ----
    #pragma unroll
    for (int it = 0; it < 4; it++) {
        int lin = tid + it*128;       // 0..511
        int row = lin >> 3;           // 0..63
        int dq  = lin & 7;            // 0..7
        float4 v = *reinterpret_cast<const float4*>(&g_qkv[(row0+row)*3*DIM + h*HD + dq*4]);
        uint32_t* qrow = reinterpret_cast<uint32_t*>(&Qs[row][0]);
        qrow[dq*2+0] = pack_bf16(v.x*scale, v.y*scale);
        qrow[dq*2+1] = pack_bf16(v.z*scale, v.w*scale);
    }
    __syncthreads();

    // ---- Q A-fragments (m16n8k16): 2 k-steps over d=32 ----
    uint32_t qa[2][4];
    {
        const uint32_t* qg  = reinterpret_cast<const uint32_t*>(&Qs[w*16 + g    ][0]);
        const uint32_t* qg8 = reinterpret_cast<const uint32_t*>(&Qs[w*16 + g + 8][0]);
        #pragma unroll
        for (int ks = 0; ks < 2; ks++) {
            qa[ks][0] = qg [ks*8 + t4];
            qa[ks][1] = qg8[ks*8 + t4];
            qa[ks][2] = qg [ks*8 + 4 + t4];
            qa[ks][3] = qg8[ks*8 + 4 + t4];
        }
    }

    float Oa[4][4];
    #pragma unroll
    for (int nt = 0; nt < 4; nt++)
        #pragma unroll
        for (int i = 0; i < 4; i++) Oa[nt][i] = 0.f;
    float l0 = 0.f, l1 = 0.f;

    // this block's key tiles: kt = half*64, half*64+128, ...  (10 tiles)
    for (int kt = half*KT; kt < NTOK; kt += 2*KT) {
        __syncthreads();     // smem reuse guard
        // ---- load K (key-major) and V (d-major), simple layouts ----
        #pragma unroll
        for (int it = 0; it < 4; it++) {
            int lin = tid + it*128;    // 0..511
            int key = lin >> 3;
            int dq  = lin & 7;
            const float* base = &g_qkv[(b*NTOK + kt + key)*3*DIM + DIM + h*HD + dq*4];
            float4 kv = *reinterpret_cast<const float4*>(base);
            uint32_t* krow = reinterpret_cast<uint32_t*>(&Ks[key][0]);
            krow[dq*2+0] = pack_bf16(kv.x, kv.y);
            krow[dq*2+1] = pack_bf16(kv.z, kv.w);
            float4 vv = *reinterpret_cast<const float4*>(base + DIM);
            *reinterpret_cast<__nv_bfloat16*>(&Vt[dq*4+0][key]) = __float2bfloat16(vv.x);
            *reinterpret_cast<__nv_bfloat16*>(&Vt[dq*4+1][key]) = __float2bfloat16(vv.y);
            *reinterpret_cast<__nv_bfloat16*>(&Vt[dq*4+2][key]) = __float2bfloat16(vv.z);
            *reinterpret_cast<__nv_bfloat16*>(&Vt[dq*4+3][key]) = __float2bfloat16(vv.w);
        }
        __syncthreads();

        // ---- S = Q K^T : 16 x 64 per warp; ldmatrix.x4 per n-tile ----
        float Sa[8][4];
        #pragma unroll
        for (int j = 0; j < 8; j++)
            #pragma unroll
            for (int i = 0; i < 4; i++) Sa[j][i] = 0.f;
        #pragma unroll
        for (int j = 0; j < 8; j++) {
            uint32_t k0, k1, k2, k3;
            ldm_x4(k0, k1, k2, k3, ks_base + (j*8 + lrow)*(KSP*2) + lquad);
            uint32_t b0[2] = {k0, k1};
            uint32_t b1[2] = {k2, k3};
            mma_bf16(Sa[j], qa[0], b0);
            mma_bf16(Sa[j], qa[1], b1);
        }

        // ---- softmax (no max) + P@V; V fragments via ldmatrix.x4 ----
        #pragma unroll
        for (int c = 0; c < 2; c++) {          // c covers kt2 = 2c, 2c+1 (32 keys)
            uint32_t vf[4][4];
            #pragma unroll
            for (int nt = 0; nt < 4; nt++)
                ldm_x4(vf[nt][0], vf[nt][1], vf[nt][2], vf[nt][3],
                       vt_base + (nt*8 + lrow)*(VSP*2) + c*64 + lquad);
            #pragma unroll
            for (int sub = 0; sub < 2; sub++) {
                int kt2 = 2*c + sub;
                float p00 = __expf(Sa[2*kt2  ][0]);
                float p01 = __expf(Sa[2*kt2  ][1]);
                float p02 = __expf(Sa[2*kt2  ][2]);
                float p03 = __expf(Sa[2*kt2  ][3]);
                float p10 = __expf(Sa[2*kt2+1][0]);
                float p11 = __expf(Sa[2*kt2+1][1]);
                float p12 = __expf(Sa[2*kt2+1][2]);
                float p13 = __expf(Sa[2*kt2+1][3]);
                l0 += p00 + p01 + p10 + p11;     // rows g
                l1 += p02 + p03 + p12 + p13;     // rows g+8
                uint32_t pa[4];
                pa[0] = pack_bf16(p00, p01);
                pa[1] = pack_bf16(p02, p03);
                pa[2] = pack_bf16(p10, p11);
                pa[3] = pack_bf16(p12, p13);
                #pragma unroll
                for (int nt = 0; nt < 4; nt++) {
                    uint32_t bfr[2] = {vf[nt][sub*2], vf[nt][sub*2+1]};
                    mma_bf16(Oa[nt], pa, bfr);
                }
            }
        }
    }

    // ---- reduce l within quad, store UNNORMALIZED partials + per-head l ----
    l0 += __shfl_xor_sync(0xffffffffu, l0, 1);
    l0 += __shfl_xor_sync(0xffffffffu, l0, 2);
    l1 += __shfl_xor_sync(0xffffffffu, l1, 1);
    l1 += __shfl_xor_sync(0xffffffffu, l1, 2);
    int r0 = row0 + w*16 + g;
    int r1 = r0 + 8;
    float* obuf = half ? g_attn2 : g_attn;
    if (t4 == 0) {
        g_l[(half*MROWS + r0)*HEADS + h] = l0;
        g_l[(half*MROWS + r1)*HEADS + h] = l1;
    }
    #pragma unroll
    for (int nt = 0; nt < 4; nt++) {
        int c = h*HD + nt*8 + t4*2;
        float2 s0; s0.x = Oa[nt][0]; s0.y = Oa[nt][1];
        float2 s1; s1.x = Oa[nt][2]; s1.y = Oa[nt][3];
        *reinterpret_cast<float2*>(&obuf[r0*DIM + c]) = s0;
        *reinterpret_cast<float2*>(&obuf[r1*DIM + c]) = s1;
    }
}

// ---------------- decoder stage 1: head projections (warp per token) ----------------
__global__ void __launch_bounds__(256) decoder_proj_kernel(
        const float* __restrict__ dWc, const float* __restrict__ dbc,
        const float* __restrict__ dWf, const float* __restrict__ dbf) {
    int wid  = blockIdx.x*8 + (threadIdx.x >> 5);
    int lane = threadIdx.x & 31;
    int b = wid / NTOK;
    int t = wid % NTOK;

    if (t < NC) {
        const float4* tok = reinterpret_cast<const float4*>(&g_tokens[(b*NTOK + t)*DIM]);
        const float4* wv  = reinterpret_cast<const float4*>(dWc);
        float4 a = tok[lane], ww = wv[lane];
        float s = a.x*ww.x + a.y*ww.y + a.z*ww.z + a.w*ww.w;
        #pragma unroll
        for (int off = 16; off > 0; off >>= 1) s += __shfl_xor_sync(0xffffffffu, s, off);
        if (lane == 0) g_c16map[b*NC + t] = s + dbc[0];
    } else {
        int p = t - NC;
        int ne = g_nedges[b];
        float s = 0.f;
        if (p < ne) {
            const float4* tok = reinterpret_cast<const float4*>(&g_tokens[(b*NTOK + t)*DIM]);
            const float4* wv  = reinterpret_cast<const float4*>(dWf);
            float4 a = tok[lane], ww = wv[lane];
            s = a.x*ww.x + a.y*ww.y + a.z*ww.z + a.w*ww.w;
            #pragma unroll
            for (int off = 16; off > 0; off >>= 1) s += __shfl_xor_sync(0xffffffffu, s, off);
            s += dbf[0];
        }
        if (lane == 0) g_fmap[b*NF + g_order[b*NF + p]] = (p < ne) ? s : 0.f;
    }
}

// ---------------- decoder stage 2: bilinear + 2 convs ----------------
__global__ void decoder_conv_kernel(const float* __restrict__ fW1, const float* __restrict__ fb1,
                                    const float* __restrict__ fW2, const float* __restrict__ fb2,
                                    float* __restrict__ out) {
    int b = blockIdx.x, t = threadIdx.x;   // t in [0,1024)
    __shared__ float c16[256];
    __shared__ float f1m[1024];
    __shared__ float f0 [1024];
    __shared__ float h0 [1024];
    __shared__ float h1 [1024];

    if (t < 256) c16[t] = g_c16map[b*NC + t];
    f1m[t] = g_fmap[b*NF + t];
    __syncthreads();

    int oy = t >> 5, ox = t & 31;
    float ys = oy * (15.f/31.f), xs = ox * (15.f/31.f);
    int y0 = (int)floorf(ys); int y1 = min(y0+1, 15); float wy = ys - y0;
    int x0 = (int)floorf(xs); int x1 = min(x0+1, 15); float wx = xs - x0;
    float cup = c16[y0*16+x0]*(1.f-wy)*(1.f-wx) + c16[y0*16+x1]*(1.f-wy)*wx
              + c16[y1*16+x0]*wy*(1.f-wx)       + c16[y1*16+x1]*wy*wx;
    f0[t] = cup;
    __syncthreads();

    #pragma unroll
    for (int oc = 0; oc < 2; oc++) {
        float a = fb1[oc];
        #pragma unroll
        for (int dy = 0; dy < 3; dy++) {
            #pragma unroll
            for (int dx = 0; dx < 3; dx++) {
                int yy = oy + dy - 1, xx = ox + dx - 1;
                float v0 = (yy < 0 || yy > 31 || xx < 0 || xx > 31) ? 0.f : f0 [yy*32+xx];
                float v1 = (yy < 0 || yy > 31 || xx < 0 || xx > 31) ? 0.f : f1m[yy*32+xx];
                a += v0 * fW1[((oc*2 + 0)*3 + dy)*3 + dx];
                a += v1 * fW1[((oc*2 + 1)*3 + dy)*3 + dx];
            }
        }
        if (oc == 0) h0[t] = fmaxf(a, 0.f); else h1[t] = fmaxf(a, 0.f);
    }
    __syncthreads();

    float a = fb2[0];
    #pragma unroll
    for (int dy = 0; dy < 3; dy++) {
        #pragma unroll
        for (int dx = 0; dx < 3; dx++) {
            int yy = oy + dy - 1, xx = ox + dx - 1;
            float v0 = (yy < 0 || yy > 31 || xx < 0 || xx > 31) ? 0.f : h0[yy*32+xx];
            float v1 = (yy < 0 || yy > 31 || xx < 0 || xx > 31) ? 0.f : h1[yy*32+xx];
            a += v0 * fW2[(0*3 + dy)*3 + dx];
            a += v1 * fW2[(3 + dy)*3 + dx];
        }
    }
    out[b*1024 + t] = a;
}

// ---------------- launch ----------------
extern "C" void kernel_launch(void* const* d_in, const int* in_sizes, int n_in,
                              void* d_out, int out_size) {
    const float* x    = (const float*)d_in[0];
    const float* Wpc  = (const float*)d_in[1];
    const float* bpc  = (const float*)d_in[2];
    const float* Wpf  = (const float*)d_in[3];
    const float* bpf  = (const float*)d_in[4];
    const float* te   = (const float*)d_in[5];
    const float* ln1g = (const float*)d_in[6];
    const float* ln1b = (const float*)d_in[7];
    const float* Wqkv = (const float*)d_in[8];
    const float* Wo   = (const float*)d_in[9];
    const float* bo   = (const float*)d_in[10];
    const float* ln2g = (const float*)d_in[11];
    const float* ln2b = (const float*)d_in[12];
    const float* W1   = (const float*)d_in[13];
    const float* b1   = (const float*)d_in[14];
    const float* W2   = (const float*)d_in[15];
    const float* b2   = (const float*)d_in[16];
    const float* dWc  = (const float*)d_in[17];
    const float* dbc  = (const float*)d_in[18];
    const float* dWf  = (const float*)d_in[19];
    const float* dbf  = (const float*)d_in[20];
    const float* fW1  = (const float*)d_in[21];
    const float* fb1  = (const float*)d_in[22];
    const float* fW2  = (const float*)d_in[23];
    const float* fb2  = (const float*)d_in[24];
    float* out = (float*)d_out;

    edge_kernel<<<BSZ, 1024>>>(x);
    patch_kernel<<<MROWS, 128>>>(x, Wpc, bpc, Wpf, bpf, te, ln1g, ln1b);

    for (int l = 0; l < NLAYERS; l++) {
        gemm_tc<128,64,256,0,false,false,false><<<dim3(6,80), 256>>>(
            BUF_Y, Wqkv + l*DIM*3*DIM, nullptr, -1, BUF_QKV, 3*DIM, DIM, nullptr, nullptr);
        flash_bf16_kernel<<<BSZ*HEADS*(NTOK/QR)*2, 128>>>();
        gemm_tc<32,128,128,0,true,true,true><<<dim3(1,320), 128>>>(
            BUF_ATTN, Wo + l*DIM*DIM, bo + l*DIM, BUF_TOKENS, BUF_TOKENS, DIM, DIM,
            ln2g + l*DIM, ln2b + l*DIM);
        gemm_tc<128,64,256,1,false,false,false><<<dim3(4,80), 256>>>(
            BUF_Y, W1 + l*DIM*2*DIM, b1 + l*2*DIM, -1, BUF_H, 2*DIM, DIM, nullptr, nullptr);
        if (l < NLAYERS-1) {
            gemm_tc<32,128,128,0,true,true,false><<<dim3(1,320), 128>>>(
                BUF_H, W2 + l*2*DIM*DIM, b2 + l*DIM, BUF_TOKENS, BUF_TOKENS, DIM, 2*DIM,
                ln1g + (l+1)*DIM, ln1b + (l+1)*DIM);
        } else {
            gemm_tc<32,128,128,0,true,false,false><<<dim3(1,320), 128>>>(
                BUF_H, W2 + l*2*DIM*DIM, b2 + l*DIM, BUF_TOKENS, BUF_TOKENS, DIM, 2*DIM,
                nullptr, nullptr);
        }
    }

    decoder_proj_kernel<<<MROWS/8, 256>>>(dWc, dbc, dWf, dbf);
    decoder_conv_kernel<<<BSZ, 1024>>>(fW1, fb1, fW2, fb2, out);
}

// round 13
// speedup vs baseline: 1.4821x; 1.4821x over previous
#include <cuda_runtime.h>
#include <cuda_bf16.h>
#include <math.h>
#include <stdint.h>

// ---------------- problem constants ----------------
#define BSZ   8
#define IMG   128
#define DIM   128
#define HEADS 4
#define HD    32
#define NLAYERS 2
#define PC    8
#define PF    4
#define HC    16
#define NC    256
#define HF    32
#define NF    1024
#define NTOK  1280           // NC + NF
#define MROWS (BSZ*NTOK)     // 10240

// ---------------- scratch (allocation-free) ----------------
__device__ float g_tokens[MROWS*DIM];
__device__ float g_y     [MROWS*DIM];
__device__ float g_qkv   [MROWS*3*DIM];
__device__ float g_attn  [MROWS*DIM];        // flash partial, key half 0 (unnormalized)
__device__ float g_attn2 [MROWS*DIM];        // flash partial, key half 1 (unnormalized)
__device__ float g_l     [2*MROWS*HEADS];    // softmax denominators [half][row][head]
__device__ float g_h     [MROWS*2*DIM];
__device__ int   g_order [BSZ*NF];
__device__ int   g_nedges[BSZ];
__device__ float g_c16map[BSZ*NC];           // decoder coarse head output
__device__ float g_fmap  [BSZ*NF];           // decoder fine head output (pixel order)

#define BUF_TOKENS 0
#define BUF_Y      1
#define BUF_QKV    2
#define BUF_ATTN   3
#define BUF_H      4

__device__ __forceinline__ float* bufsel(int s) {
    switch (s) {
        case BUF_TOKENS: return g_tokens;
        case BUF_Y:      return g_y;
        case BUF_QKV:    return g_qkv;
        case BUF_ATTN:   return g_attn;
        case BUF_H:      return g_h;
    }
    return nullptr;
}

// ---------------- mma helpers ----------------
__device__ __forceinline__ uint32_t f2tf(float x) {
    uint32_t u;
    asm("cvt.rna.tf32.f32 %0, %1;" : "=r"(u) : "f"(x));
    return u;
}

__device__ __forceinline__ void mma_tf32(float* c, const uint32_t* a, const uint32_t* b) {
    asm volatile(
        "mma.sync.aligned.m16n8k8.row.col.f32.tf32.tf32.f32 "
        "{%0,%1,%2,%3}, {%4,%5,%6,%7}, {%8,%9}, {%0,%1,%2,%3};\n"
        : "+f"(c[0]), "+f"(c[1]), "+f"(c[2]), "+f"(c[3])
        : "r"(a[0]), "r"(a[1]), "r"(a[2]), "r"(a[3]), "r"(b[0]), "r"(b[1]));
}

__device__ __forceinline__ void mma_bf16(float* c, const uint32_t* a, const uint32_t* b) {
    asm volatile(
        "mma.sync.aligned.m16n8k16.row.col.f32.bf16.bf16.f32 "
        "{%0,%1,%2,%3}, {%4,%5,%6,%7}, {%8,%9}, {%0,%1,%2,%3};\n"
        : "+f"(c[0]), "+f"(c[1]), "+f"(c[2]), "+f"(c[3])
        : "r"(a[0]), "r"(a[1]), "r"(a[2]), "r"(a[3]), "r"(b[0]), "r"(b[1]));
}

// pack two floats into bf16x2: low half = lo, high half = hi
__device__ __forceinline__ uint32_t pack_bf16(float lo, float hi) {
    uint32_t d;
    asm("cvt.rn.bf16x2.f32 %0, %1, %2;" : "=r"(d) : "f"(hi), "f"(lo));
    return d;
}

// ---------------- edge map + stable partition order (ballot scan) ----------------
__device__ __forceinline__ float padpx(const float* m, int y, int x) {
    return (y < 0 || y >= IMG || x < 0 || x >= IMG) ? 0.f : m[y*IMG + x];
}

__global__ void edge_kernel(const float* __restrict__ x) {
    int b = blockIdx.x, t = threadIdx.x;           // t in [0,1024)
    const float* img = x + b*IMG*IMG;
    int gy = t >> 5, gx = t & 31;
    float e = 0.f;
    #pragma unroll
    for (int wy = 0; wy < 4; wy++) {
        #pragma unroll
        for (int wx = 0; wx < 4; wx++) {
            int y = gy*4 + wy, xx = gx*4 + wx;
            float sx = padpx(img,y-1,xx+1) - padpx(img,y-1,xx-1)
                     + 2.f*(padpx(img,y,xx+1) - padpx(img,y,xx-1))
                     + padpx(img,y+1,xx+1) - padpx(img,y+1,xx-1);
            float sy = padpx(img,y+1,xx-1) + 2.f*padpx(img,y+1,xx) + padpx(img,y+1,xx+1)
                     - padpx(img,y-1,xx-1) - 2.f*padpx(img,y-1,xx) - padpx(img,y-1,xx+1);
            e += sqrtf(sx*sx + sy*sy);
        }
    }
    e *= (1.f/16.f);

    int w = t >> 5, lane = t & 31;
    __shared__ float wsumf[32];
    __shared__ int   wsum [32];
    __shared__ float smean;
    __shared__ int   s_ne;

    float s = e;
    #pragma unroll
    for (int off = 16; off > 0; off >>= 1) s += __shfl_xor_sync(0xffffffffu, s, off);
    if (lane == 0) wsumf[w] = s;
    __syncthreads();
    if (w == 0) {
        float v = wsumf[lane];
        #pragma unroll
        for (int off = 16; off > 0; off >>= 1) v += __shfl_xor_sync(0xffffffffu, v, off);
        if (lane == 0) smean = v * (1.f/1024.f);
    }
    __syncthreads();

    int mk = (e > smean) ? 1 : 0;
    unsigned bal = __ballot_sync(0xffffffffu, mk);
    unsigned lemask = 0xffffffffu >> (31 - lane);
    int rank_in_warp = __popc(bal & lemask);
    if (lane == 0) wsum[w] = __popc(bal);
    __syncthreads();
    if (w == 0) {
        int v = wsum[lane];
        #pragma unroll
        for (int off = 1; off < 32; off <<= 1) {
            int n = __shfl_up_sync(0xffffffffu, v, off);
            if (lane >= off) v += n;
        }
        wsum[lane] = v;
        if (lane == 31) s_ne = v;
    }
    __syncthreads();
    int prefix = (w > 0) ? wsum[w-1] : 0;
    int rank = prefix + rank_in_warp;
    int ne = s_ne;
    int pos = mk ? (rank - 1) : (ne + t - rank);
    g_order[b*NF + pos] = t;
    if (t == 0) g_nedges[b] = ne;
}

// ---------------- patch embed + token assembly + fused first LN ----------------
__global__ void patch_kernel(const float* __restrict__ x,
                             const float* __restrict__ Wpc, const float* __restrict__ bpc,
                             const float* __restrict__ Wpf, const float* __restrict__ bpf,
                             const float* __restrict__ te,
                             const float* __restrict__ lng, const float* __restrict__ lnb) {
    int blk = blockIdx.x;
    int b = blk / NTOK, t = blk % NTOK;
    int d = threadIdx.x;                 // 128
    const float* img = x + b*IMG*IMG;
    __shared__ float sp[64];
    float acc;

    if (t < NC) {
        int hp = t / HC, wp = t % HC;
        if (d < 64) {
            int py = d >> 3, px = d & 7;
            sp[d] = img[(hp*PC + py)*IMG + wp*PC + px];
        }
        __syncthreads();
        acc = bpc[d] + te[d];
        #pragma unroll 8
        for (int p = 0; p < 64; p++) acc += sp[p] * Wpc[p*DIM + d];
    } else {
        int p  = t - NC;
        int ne = g_nedges[b];
        acc = te[DIM + d];
        if (p < ne) {
            int ord = g_order[b*NF + p];
            int hp = ord / HF, wp = ord % HF;
            if (d < 16) {
                int py = d >> 2, px = d & 3;
                sp[d] = img[(hp*PF + py)*IMG + wp*PF + px];
            }
            __syncthreads();
            acc += bpf[d];
            #pragma unroll
            for (int e = 0; e < 16; e++) acc += sp[e] * Wpf[e*DIM + d];
        }
    }

    float v = acc;
    float s = v, q = v*v;
    #pragma unroll
    for (int off = 16; off > 0; off >>= 1) {
        s += __shfl_down_sync(0xffffffffu, s, off);
        q += __shfl_down_sync(0xffffffffu, q, off);
    }
    __shared__ float ss[4], qq[4];
    int w = d >> 5, lane = d & 31;
    if (lane == 0) { ss[w] = s; qq[w] = q; }
    __syncthreads();
    float S = ss[0]+ss[1]+ss[2]+ss[3];
    float Q = qq[0]+qq[1]+qq[2]+qq[3];
    float mean = S * (1.f/DIM);
    float var  = Q * (1.f/DIM) - mean*mean;
    int row = b*NTOK + t;
    g_tokens[row*DIM + d] = v;
    g_y[row*DIM + d] = (v - mean) * rsqrtf(var + 1e-5f) * lng[d] + lnb[d];
}

// ---------------- tf32 tensor-core GEMM ----------------
template<int BM, int BN, int THREADS, int ACT, bool RES, bool LNOUT, bool COMBINE>
__global__ void __launch_bounds__(THREADS) gemm_tc(
        int aSel, const float* __restrict__ Bw, const float* __restrict__ bias,
        int resSel, int outSel, int N, int K,
        const float* __restrict__ lng, const float* __restrict__ lnb) {
    const float* A = bufsel(aSel);
    float* C = bufsel(outSel);
    const float* R = RES ? bufsel(resSel) : nullptr;

    constexpr int WARPS = THREADS/32;
    constexpr int WN = BN/32;
    constexpr int WM = WARPS/WN;
    static_assert(BM/WM == 32, "rows-per-warp must be 32");

    constexpr int APAD = BM + 8;
    constexpr int BPAD = BN + 8;
    constexpr int CPAD = BN + 5;
    constexpr int ABYTES = 16*APAD*4;
    constexpr int BBYTES = 16*BPAD*4;
    constexpr int CBYTES = LNOUT ? BM*CPAD*4 : 0;
    constexpr int SBYTES = (ABYTES+BBYTES) > CBYTES ? (ABYTES+BBYTES) : CBYTES;
    __shared__ alignas(16) char raw[SBYTES];
    uint32_t (*As)[APAD] = reinterpret_cast<uint32_t(*)[APAD]>(raw);
    uint32_t (*Bs)[BPAD] = reinterpret_cast<uint32_t(*)[BPAD]>(raw + ABYTES);
    float    (*Cs)[CPAD] = reinterpret_cast<float(*)[CPAD]>(raw);
    __shared__ float s_mu[BM], s_rs[BM];
    __shared__ float s_rinv[COMBINE ? BM*HEADS : 1];

    int tid = threadIdx.x;
    int lane = tid & 31;
    int w = tid >> 5;
    int wm = w / WN;
    int wn = w % WN;
    int g  = lane >> 2;
    int t4 = lane & 3;

    int row0 = blockIdx.y * BM;
    int col0 = blockIdx.x * BN;

    if (COMBINE) {
        if (tid < BM*HEADS) {
            int r  = row0 + tid/HEADS;
            int hh = tid % HEADS;
            s_rinv[tid] = 1.f / (g_l[r*HEADS + hh] + g_l[(MROWS + r)*HEADS + hh]);
        }
        __syncthreads();
    }

    float acc[2][4][4];
    #pragma unroll
    for (int mt = 0; mt < 2; mt++)
        #pragma unroll
        for (int nt = 0; nt < 4; nt++)
            #pragma unroll
            for (int i = 0; i < 4; i++) acc[mt][nt][i] = 0.f;

    for (int k0 = 0; k0 < K; k0 += 16) {
        #pragma unroll
        for (int i = 0; i < BM*16/(THREADS*4); i++) {
            int lin = tid + i*THREADS;
            int row = lin >> 2;
            int kq  = lin & 3;
            int idx = (row0 + row)*K + k0 + kq*4;
            float4 v;
            if (COMBINE) {
                float4 va = *reinterpret_cast<const float4*>(&g_attn [idx]);
                float4 vb = *reinterpret_cast<const float4*>(&g_attn2[idx]);
                float ri = s_rinv[row*HEADS + ((k0 + kq*4) >> 5)];
                v.x = (va.x+vb.x)*ri; v.y = (va.y+vb.y)*ri;
                v.z = (va.z+vb.z)*ri; v.w = (va.w+vb.w)*ri;
            } else {
                v = *reinterpret_cast<const float4*>(&A[idx]);
            }
            As[kq*4+0][row] = f2tf(v.x);
            As[kq*4+1][row] = f2tf(v.y);
            As[kq*4+2][row] = f2tf(v.z);
            As[kq*4+3][row] = f2tf(v.w);
        }
        #pragma unroll
        for (int i = 0; i < BN*16/(THREADS*4); i++) {
            int lin = tid + i*THREADS;
            int k  = lin / (BN/4);
            int cq = lin % (BN/4);
            float4 v = *reinterpret_cast<const float4*>(&Bw[(k0 + k)*N + col0 + cq*4]);
            uint4 u;
            u.x = f2tf(v.x); u.y = f2tf(v.y); u.z = f2tf(v.z); u.w = f2tf(v.w);
            *reinterpret_cast<uint4*>(&Bs[k][cq*4]) = u;
        }
        __syncthreads();

        #pragma unroll
        for (int ks = 0; ks < 2; ks++) {
            int kk = ks*8;
            uint32_t af[2][4], bf[4][2];
            #pragma unroll
            for (int mt = 0; mt < 2; mt++) {
                int br = wm*32 + mt*16;
                af[mt][0] = As[kk + t4    ][br + g    ];
                af[mt][1] = As[kk + t4    ][br + g + 8];
                af[mt][2] = As[kk + t4 + 4][br + g    ];
                af[mt][3] = As[kk + t4 + 4][br + g + 8];
            }
            #pragma unroll
            for (int nt = 0; nt < 4; nt++) {
                int bc = wn*32 + nt*8;
                bf[nt][0] = Bs[kk + t4    ][bc + g];
                bf[nt][1] = Bs[kk + t4 + 4][bc + g];
            }
            #pragma unroll
            for (int mt = 0; mt < 2; mt++)
                #pragma unroll
                for (int nt = 0; nt < 4; nt++)
                    mma_tf32(acc[mt][nt], af[mt], bf[nt]);
        }
        __syncthreads();
    }

    #pragma unroll
    for (int mt = 0; mt < 2; mt++) {
        #pragma unroll
        for (int nt = 0; nt < 4; nt++) {
            #pragma unroll
            for (int half = 0; half < 2; half++) {
                int lr = wm*32 + mt*16 + g + half*8;
                int lc = wn*32 + nt*8 + t4*2;
                int r  = row0 + lr;
                int c  = col0 + lc;
                float v0 = acc[mt][nt][half*2+0];
                float v1 = acc[mt][nt][half*2+1];
                if (bias) { v0 += bias[c]; v1 += bias[c+1]; }
                if (ACT == 1) {
                    v0 = 0.5f*v0*(1.f + erff(v0*0.70710678118654752f));
                    v1 = 0.5f*v1*(1.f + erff(v1*0.70710678118654752f));
                }
                if (RES) { v0 += R[r*N + c]; v1 += R[r*N + c + 1]; }
                float2 st; st.x = v0; st.y = v1;
                *reinterpret_cast<float2*>(&C[r*N + c]) = st;
                if (LNOUT) { Cs[lr][lc] = v0; Cs[lr][lc+1] = v1; }
            }
        }
    }

    if (LNOUT) {
        __syncthreads();
        if (tid < BM) {
            float s = 0.f, q = 0.f;
            #pragma unroll 8
            for (int c = 0; c < BN; c++) {
                float v = Cs[tid][c];
                s += v; q += v*v;
            }
            float mean = s * (1.f/BN);
            float var  = q * (1.f/BN) - mean*mean;
            s_mu[tid] = mean;
            s_rs[tid] = rsqrtf(var + 1e-5f);
        }
        __syncthreads();
        #pragma unroll
        for (int i = 0; i < BM*BN/THREADS; i++) {
            int lin = tid + i*THREADS;
            int r = lin / BN;
            int c = lin % BN;
            float v = (Cs[r][c] - s_mu[r]) * s_rs[r] * lng[c] + lnb[c];
            g_y[(row0 + r)*BN + c] = v;
        }
    }
}

// ---------------- bf16 tensor-core flash attention (key-split x2) ----------------
// One block per (b, h, 64-query tile, key-half). 4 warps x 16 q-rows.
// R9 variant (best measured: 53.7us): simple layouts + split LDS.32 fragment loads.
#define QR 64     // q rows per block
#define KT 64     // keys per staged tile
#define QSP 40    // Q row stride (bf16)
#define KSP 40    // K row stride (bf16)
#define VSP 72    // Vt row stride (bf16)
__global__ void __launch_bounds__(128) flash_bf16_kernel() {
    __shared__ alignas(16) uint16_t Qs[QR][QSP];
    __shared__ alignas(16) uint16_t Ks[KT][KSP];
    __shared__ alignas(16) uint16_t Vt[HD][VSP];

    int tid = threadIdx.x;
    int lane = tid & 31;
    int w = tid >> 5;                 // 0..3
    int g = lane >> 2;                // 0..7
    int t4 = lane & 3;                // 0..3

    int half = blockIdx.x & 1;
    int rest = blockIdx.x >> 1;
    int qt = rest % (NTOK/QR);                  // 0..19
    int h  = (rest / (NTOK/QR)) % HEADS;
    int b  = rest / ((NTOK/QR)*HEADS);
    int row0 = b*NTOK + qt*QR;
    const float scale = 0.17677669529663687f;   // 1/sqrt(32)

    // ---- stage Q (64 x 32), scaled, bf16 ----
    #pragma unroll
    for (int it = 0; it < 4; it++) {
        int lin = tid + it*128;       // 0..511
        int row = lin >> 3;           // 0..63
        int dq  = lin & 7;            // 0..7
        float4 v = *reinterpret_cast<const float4*>(&g_qkv[(row0+row)*3*DIM + h*HD + dq*4]);
        uint32_t* qrow = reinterpret_cast<uint32_t*>(&Qs[row][0]);
        qrow[dq*2+0] = pack_bf16(v.x*scale, v.y*scale);
        qrow[dq*2+1] = pack_bf16(v.z*scale, v.w*scale);
    }
    __syncthreads();

    // ---- Q A-fragments (m16n8k16): 2 k-steps over d=32 ----
    uint32_t qa[2][4];
    {
        const uint32_t* qg  = reinterpret_cast<const uint32_t*>(&Qs[w*16 + g    ][0]);
        const uint32_t* qg8 = reinterpret_cast<const uint32_t*>(&Qs[w*16 + g + 8][0]);
        #pragma unroll
        for (int ks = 0; ks < 2; ks++) {
            qa[ks][0] = qg [ks*8 + t4];
            qa[ks][1] = qg8[ks*8 + t4];
            qa[ks][2] = qg [ks*8 + 4 + t4];
            qa[ks][3] = qg8[ks*8 + 4 + t4];
        }
    }

    float Oa[4][4];
    #pragma unroll
    for (int nt = 0; nt < 4; nt++)
        #pragma unroll
        for (int i = 0; i < 4; i++) Oa[nt][i] = 0.f;
    float l0 = 0.f, l1 = 0.f;

    // this block's key tiles: kt = half*64, half*64+128, ...  (10 tiles)
    for (int kt = half*KT; kt < NTOK; kt += 2*KT) {
        __syncthreads();     // smem reuse guard
        // ---- load K (key-major) and V (transposed, d-major), bf16 ----
        #pragma unroll
        for (int it = 0; it < 4; it++) {
            int lin = tid + it*128;    // 0..511
            int key = lin >> 3;
            int dq  = lin & 7;
            const float* base = &g_qkv[(b*NTOK + kt + key)*3*DIM + DIM + h*HD + dq*4];
            float4 kv = *reinterpret_cast<const float4*>(base);
            uint32_t* krow = reinterpret_cast<uint32_t*>(&Ks[key][0]);
            krow[dq*2+0] = pack_bf16(kv.x, kv.y);
            krow[dq*2+1] = pack_bf16(kv.z, kv.w);
            float4 vv = *reinterpret_cast<const float4*>(base + DIM);
            *reinterpret_cast<__nv_bfloat16*>(&Vt[dq*4+0][key]) = __float2bfloat16(vv.x);
            *reinterpret_cast<__nv_bfloat16*>(&Vt[dq*4+1][key]) = __float2bfloat16(vv.y);
            *reinterpret_cast<__nv_bfloat16*>(&Vt[dq*4+2][key]) = __float2bfloat16(vv.z);
            *reinterpret_cast<__nv_bfloat16*>(&Vt[dq*4+3][key]) = __float2bfloat16(vv.w);
        }
        __syncthreads();

        // ---- S = Q K^T : 16 x 64 per warp (8 n-tiles x 2 k-steps) ----
        float Sa[8][4];
        #pragma unroll
        for (int j = 0; j < 8; j++)
            #pragma unroll
            for (int i = 0; i < 4; i++) Sa[j][i] = 0.f;
        #pragma unroll
        for (int ks = 0; ks < 2; ks++) {
            #pragma unroll
            for (int j = 0; j < 8; j++) {
                const uint32_t* krow = reinterpret_cast<const uint32_t*>(&Ks[j*8 + g][0]);
                uint32_t bfr[2];
                bfr[0] = krow[ks*8 + t4];
                bfr[1] = krow[ks*8 + 4 + t4];
                mma_bf16(Sa[j], qa[ks], bfr);
            }
        }

        // ---- softmax (no max) + P@V; accumulator -> A fragment directly ----
        #pragma unroll
        for (int kt2 = 0; kt2 < 4; kt2++) {
            float p00 = __expf(Sa[2*kt2  ][0]);
            float p01 = __expf(Sa[2*kt2  ][1]);
            float p02 = __expf(Sa[2*kt2  ][2]);
            float p03 = __expf(Sa[2*kt2  ][3]);
            float p10 = __expf(Sa[2*kt2+1][0]);
            float p11 = __expf(Sa[2*kt2+1][1]);
            float p12 = __expf(Sa[2*kt2+1][2]);
            float p13 = __expf(Sa[2*kt2+1][3]);
            l0 += p00 + p01 + p10 + p11;     // rows g
            l1 += p02 + p03 + p12 + p13;     // rows g+8
            uint32_t pa[4];
            pa[0] = pack_bf16(p00, p01);
            pa[1] = pack_bf16(p02, p03);
            pa[2] = pack_bf16(p10, p11);
            pa[3] = pack_bf16(p12, p13);
            #pragma unroll
            for (int nt = 0; nt < 4; nt++) {
                const uint32_t* vrow = reinterpret_cast<const uint32_t*>(&Vt[nt*8 + g][0]);
                uint32_t bfr[2];
                bfr[0] = vrow[kt2*8 + t4];
                bfr[1] = vrow[kt2*8 + 4 + t4];
                mma_bf16(Oa[nt], pa, bfr);
            }
        }
    }

    // ---- reduce l within quad, store UNNORMALIZED partials + per-head l ----
    l0 += __shfl_xor_sync(0xffffffffu, l0, 1);
    l0 += __shfl_xor_sync(0xffffffffu, l0, 2);
    l1 += __shfl_xor_sync(0xffffffffu, l1, 1);
    l1 += __shfl_xor_sync(0xffffffffu, l1, 2);
    int r0 = row0 + w*16 + g;
    int r1 = r0 + 8;
    float* obuf = half ? g_attn2 : g_attn;
    if (t4 == 0) {
        g_l[(half*MROWS + r0)*HEADS + h] = l0;
        g_l[(half*MROWS + r1)*HEADS + h] = l1;
    }
    #pragma unroll
    for (int nt = 0; nt < 4; nt++) {
        int c = h*HD + nt*8 + t4*2;
        float2 s0; s0.x = Oa[nt][0]; s0.y = Oa[nt][1];
        float2 s1; s1.x = Oa[nt][2]; s1.y = Oa[nt][3];
        *reinterpret_cast<float2*>(&obuf[r0*DIM + c]) = s0;
        *reinterpret_cast<float2*>(&obuf[r1*DIM + c]) = s1;
    }
}

// ---------------- decoder stage 1: head projections (warp per token) ----------------
__global__ void __launch_bounds__(256) decoder_proj_kernel(
        const float* __restrict__ dWc, const float* __restrict__ dbc,
        const float* __restrict__ dWf, const float* __restrict__ dbf) {
    int wid  = blockIdx.x*8 + (threadIdx.x >> 5);
    int lane = threadIdx.x & 31;
    int b = wid / NTOK;
    int t = wid % NTOK;

    if (t < NC) {
        const float4* tok = reinterpret_cast<const float4*>(&g_tokens[(b*NTOK + t)*DIM]);
        const float4* wv  = reinterpret_cast<const float4*>(dWc);
        float4 a = tok[lane], ww = wv[lane];
        float s = a.x*ww.x + a.y*ww.y + a.z*ww.z + a.w*ww.w;
        #pragma unroll
        for (int off = 16; off > 0; off >>= 1) s += __shfl_xor_sync(0xffffffffu, s, off);
        if (lane == 0) g_c16map[b*NC + t] = s + dbc[0];
    } else {
        int p = t - NC;
        int ne = g_nedges[b];
        float s = 0.f;
        if (p < ne) {
            const float4* tok = reinterpret_cast<const float4*>(&g_tokens[(b*NTOK + t)*DIM]);
            const float4* wv  = reinterpret_cast<const float4*>(dWf);
            float4 a = tok[lane], ww = wv[lane];
            s = a.x*ww.x + a.y*ww.y + a.z*ww.z + a.w*ww.w;
            #pragma unroll
            for (int off = 16; off > 0; off >>= 1) s += __shfl_xor_sync(0xffffffffu, s, off);
            s += dbf[0];
        }
        if (lane == 0) g_fmap[b*NF + g_order[b*NF + p]] = (p < ne) ? s : 0.f;
    }
}

// ---------------- decoder stage 2: bilinear + 2 convs ----------------
__global__ void decoder_conv_kernel(const float* __restrict__ fW1, const float* __restrict__ fb1,
                                    const float* __restrict__ fW2, const float* __restrict__ fb2,
                                    float* __restrict__ out) {
    int b = blockIdx.x, t = threadIdx.x;   // t in [0,1024)
    __shared__ float c16[256];
    __shared__ float f1m[1024];
    __shared__ float f0 [1024];
    __shared__ float h0 [1024];
    __shared__ float h1 [1024];

    if (t < 256) c16[t] = g_c16map[b*NC + t];
    f1m[t] = g_fmap[b*NF + t];
    __syncthreads();

    int oy = t >> 5, ox = t & 31;
    float ys = oy * (15.f/31.f), xs = ox * (15.f/31.f);
    int y0 = (int)floorf(ys); int y1 = min(y0+1, 15); float wy = ys - y0;
    int x0 = (int)floorf(xs); int x1 = min(x0+1, 15); float wx = xs - x0;
    float cup = c16[y0*16+x0]*(1.f-wy)*(1.f-wx) + c16[y0*16+x1]*(1.f-wy)*wx
              + c16[y1*16+x0]*wy*(1.f-wx)       + c16[y1*16+x1]*wy*wx;
    f0[t] = cup;
    __syncthreads();

    #pragma unroll
    for (int oc = 0; oc < 2; oc++) {
        float a = fb1[oc];
        #pragma unroll
        for (int dy = 0; dy < 3; dy++) {
            #pragma unroll
            for (int dx = 0; dx < 3; dx++) {
                int yy = oy + dy - 1, xx = ox + dx - 1;
                float v0 = (yy < 0 || yy > 31 || xx < 0 || xx > 31) ? 0.f : f0 [yy*32+xx];
                float v1 = (yy < 0 || yy > 31 || xx < 0 || xx > 31) ? 0.f : f1m[yy*32+xx];
                a += v0 * fW1[((oc*2 + 0)*3 + dy)*3 + dx];
                a += v1 * fW1[((oc*2 + 1)*3 + dy)*3 + dx];
            }
        }
        if (oc == 0) h0[t] = fmaxf(a, 0.f); else h1[t] = fmaxf(a, 0.f);
    }
    __syncthreads();

    float a = fb2[0];
    #pragma unroll
    for (int dy = 0; dy < 3; dy++) {
        #pragma unroll
        for (int dx = 0; dx < 3; dx++) {
            int yy = oy + dy - 1, xx = ox + dx - 1;
            float v0 = (yy < 0 || yy > 31 || xx < 0 || xx > 31) ? 0.f : h0[yy*32+xx];
            float v1 = (yy < 0 || yy > 31 || xx < 0 || xx > 31) ? 0.f : h1[yy*32+xx];
            a += v0 * fW2[(0*3 + dy)*3 + dx];
            a += v1 * fW2[(3 + dy)*3 + dx];
        }
    }
    out[b*1024 + t] = a;
}

// ---------------- launch ----------------
extern "C" void kernel_launch(void* const* d_in, const int* in_sizes, int n_in,
                              void* d_out, int out_size) {
    const float* x    = (const float*)d_in[0];
    const float* Wpc  = (const float*)d_in[1];
    const float* bpc  = (const float*)d_in[2];
    const float* Wpf  = (const float*)d_in[3];
    const float* bpf  = (const float*)d_in[4];
    const float* te   = (const float*)d_in[5];
    const float* ln1g = (const float*)d_in[6];
    const float* ln1b = (const float*)d_in[7];
    const float* Wqkv = (const float*)d_in[8];
    const float* Wo   = (const float*)d_in[9];
    const float* bo   = (const float*)d_in[10];
    const float* ln2g = (const float*)d_in[11];
    const float* ln2b = (const float*)d_in[12];
    const float* W1   = (const float*)d_in[13];
    const float* b1   = (const float*)d_in[14];
    const float* W2   = (const float*)d_in[15];
    const float* b2   = (const float*)d_in[16];
    const float* dWc  = (const float*)d_in[17];
    const float* dbc  = (const float*)d_in[18];
    const float* dWf  = (const float*)d_in[19];
    const float* dbf  = (const float*)d_in[20];
    const float* fW1  = (const float*)d_in[21];
    const float* fb1  = (const float*)d_in[22];
    const float* fW2  = (const float*)d_in[23];
    const float* fb2  = (const float*)d_in[24];
    float* out = (float*)d_out;

    edge_kernel<<<BSZ, 1024>>>(x);
    patch_kernel<<<MROWS, 128>>>(x, Wpc, bpc, Wpf, bpf, te, ln1g, ln1b);

    for (int l = 0; l < NLAYERS; l++) {
        gemm_tc<128,64,256,0,false,false,false><<<dim3(6,80), 256>>>(
            BUF_Y, Wqkv + l*DIM*3*DIM, nullptr, -1, BUF_QKV, 3*DIM, DIM, nullptr, nullptr);
        flash_bf16_kernel<<<BSZ*HEADS*(NTOK/QR)*2, 128>>>();
        gemm_tc<32,128,128,0,true,true,true><<<dim3(1,320), 128>>>(
            BUF_ATTN, Wo + l*DIM*DIM, bo + l*DIM, BUF_TOKENS, BUF_TOKENS, DIM, DIM,
            ln2g + l*DIM, ln2b + l*DIM);
        gemm_tc<128,64,256,1,false,false,false><<<dim3(4,80), 256>>>(
            BUF_Y, W1 + l*DIM*2*DIM, b1 + l*2*DIM, -1, BUF_H, 2*DIM, DIM, nullptr, nullptr);
        if (l < NLAYERS-1) {
            gemm_tc<32,128,128,0,true,true,false><<<dim3(1,320), 128>>>(
                BUF_H, W2 + l*2*DIM*DIM, b2 + l*DIM, BUF_TOKENS, BUF_TOKENS, DIM, 2*DIM,
                ln1g + (l+1)*DIM, ln1b + (l+1)*DIM);
        } else {
            gemm_tc<32,128,128,0,true,false,false><<<dim3(1,320), 128>>>(
                BUF_H, W2 + l*2*DIM*DIM, b2 + l*DIM, BUF_TOKENS, BUF_TOKENS, DIM, 2*DIM,
                nullptr, nullptr);
        }
    }

    decoder_proj_kernel<<<MROWS/8, 256>>>(dWc, dbc, dWf, dbf);
    decoder_conv_kernel<<<BSZ, 1024>>>(fW1, fb1, fW2, fb2, out);
}